// round 3
// baseline (speedup 1.0000x reference)
#include <cuda_runtime.h>
#include <math.h>

#define NN 100000
#define EE 3200000
#define DD 64
#define CH (NN*DD)          // 6,400,000 elements per XM chunk
#define XMW 384             // 6*64 columns in concat buffer

// ---------------- scratch (static device allocations; no cudaMalloc) --------
__device__ float d_deg[3*NN];
__device__ float d_dinv[3*NN];
__device__ float d_norm[3*EE];         // per-edge norm, per graph (38.4 MB)
__device__ float d_h[NN*DD];           // dense GEMM output (25.6 MB)
__device__ float d_acc[NN*DD];         // scatter accumulation target (25.6 MB, L2-resident)
__device__ float d_XM[(size_t)NN*XMW]; // concat(g1,g2,c1,c2,f1,f2) [N,384]
__device__ float d_csum[6];
__device__ float d_att[6];

// vector reduction to global memory (sm_90+); scalar fallback otherwise
__device__ __forceinline__ void red_add_v4(float* p, float a, float b, float c, float d) {
#if defined(__CUDA_ARCH__) && (__CUDA_ARCH__ >= 900)
    asm volatile("red.global.add.v4.f32 [%0], {%1,%2,%3,%4};"
                 :: "l"(p), "f"(a), "f"(b), "f"(c), "f"(d) : "memory");
#else
    atomicAdd(p + 0, a); atomicAdd(p + 1, b);
    atomicAdd(p + 2, c); atomicAdd(p + 3, d);
#endif
}

// ---------------- kernels ---------------------------------------------------

__global__ void k_init() {
    int t = blockIdx.x * 256 + threadIdx.x;
    if (t < 3*NN) d_deg[t] = 1.0f;          // self-loop contributes weight 1
    if (t < 6)    d_csum[t] = 0.0f;
}

__global__ void k_deg(const int* __restrict__ cols, const float* __restrict__ w, int g) {
    int t = blockIdx.x * 256 + threadIdx.x;
    if (t < EE) atomicAdd(&d_deg[g*NN + cols[t]], w[t]);
}

__global__ void k_dinv() {
    int t = blockIdx.x * 256 + threadIdx.x;
    if (t < 3*NN) {
        float d = d_deg[t];
        d_dinv[t] = (d > 0.0f) ? rsqrtf(d) : 0.0f;
    }
}

__global__ void k_norm(const int* __restrict__ rows, const int* __restrict__ cols,
                       const float* __restrict__ w, int g) {
    int t = blockIdx.x * 256 + threadIdx.x;
    if (t < EE)
        d_norm[(size_t)g*EE + t] = d_dinv[g*NN + rows[t]] * w[t] * d_dinv[g*NN + cols[t]];
}

// H[N,64] = X @ W. src=0: external x [N,64]; src=1: XM slot at column xmoff.
__global__ void __launch_bounds__(128) k_gemm(const float* __restrict__ X, int src, int xmoff,
                                              const float* __restrict__ W) {
    __shared__ float Ws[64*64];
    int tid = threadIdx.x;
    for (int i = tid; i < 64*64; i += 128) Ws[i] = W[i];
    __syncthreads();
    int row = blockIdx.x * 128 + tid;
    if (row >= NN) return;
    const float* xr = src ? (d_XM + (size_t)row * XMW + xmoff)
                          : (X + (size_t)row * DD);
    float acc[64];
#pragma unroll
    for (int j = 0; j < 64; j++) acc[j] = 0.0f;
    for (int k = 0; k < 64; k++) {
        float xv = xr[k];
        const float4* wr = (const float4*)(Ws + k*64);
#pragma unroll
        for (int j4 = 0; j4 < 16; j4++) {
            float4 wv = wr[j4];
            acc[j4*4+0] += xv * wv.x;
            acc[j4*4+1] += xv * wv.y;
            acc[j4*4+2] += xv * wv.z;
            acc[j4*4+3] += xv * wv.w;
        }
    }
    float4* hr = (float4*)(d_h + (size_t)row * 64);
#pragma unroll
    for (int j4 = 0; j4 < 16; j4++)
        hr[j4] = make_float4(acc[j4*4], acc[j4*4+1], acc[j4*4+2], acc[j4*4+3]);
}

// acc init: bias + self-loop term  (norm_self = dinv*1*dinv)
__global__ void k_initacc(int g, const float* __restrict__ b) {
    int t = blockIdx.x * 256 + threadIdx.x;
    if (t < CH) {
        int n = t >> 6, d = t & 63;
        float dv = d_dinv[g*NN + n];
        d_acc[t] = b[d] + dv * dv * d_h[t];
    }
}

// scatter: 16 threads/edge, 4 floats/thread, red.v4 into contiguous d_acc
__global__ void __launch_bounds__(256) k_scatter(const int* __restrict__ rows,
                                                 const int* __restrict__ cols, int g) {
    int t = blockIdx.x * 256 + threadIdx.x;   // < EE*16 = 51.2M
    int e = t >> 4;
    int q = (t & 15) * 4;
    if (e >= EE) return;
    int r = __ldg(rows + e);
    int c = __ldg(cols + e);
    float nm = __ldg(&d_norm[(size_t)g*EE + e]);
    float4 v = *(const float4*)(d_h + (size_t)r*64 + q);
    float* p = d_acc + (size_t)c*64 + q;
    red_add_v4(p, nm*v.x, nm*v.y, nm*v.z, nm*v.w);
}

// relu(d_acc) -> XM slot at column off
__global__ void k_relu_store(int off) {
    int t = blockIdx.x * 256 + threadIdx.x;
    if (t < CH) {
        float v = d_acc[t];
        d_XM[(size_t)(t >> 6) * XMW + off + (t & 63)] = v > 0.0f ? v : 0.0f;
    }
}

// per-chunk sums of flat XM (chunk = flat_index / 6.4M). 16 elems/thread,
// warp-uniform chunk (512 | 6.4M), warp-reduce then one RED per warp.
__global__ void k_csum() {
    int t = blockIdx.x * 256 + threadIdx.x;   // 2.4M threads
    size_t base = (size_t)t * 16;
    int chunk = (int)(base / (size_t)CH);
    const float4* p = (const float4*)(d_XM + base);
    float s = 0.0f;
#pragma unroll
    for (int i = 0; i < 4; i++) { float4 v = p[i]; s += v.x + v.y + v.z + v.w; }
#pragma unroll
    for (int o = 16; o > 0; o >>= 1) s += __shfl_down_sync(0xffffffffu, s, o);
    if ((threadIdx.x & 31) == 0) atomicAdd(&d_csum[chunk], s);
}

__global__ void k_mlp(const float* __restrict__ fc1w, const float* __restrict__ fc1b,
                      const float* __restrict__ fc2w, const float* __restrict__ fc2b) {
    if (threadIdx.x != 0 || blockIdx.x != 0) return;
    float a[6];
#pragma unroll
    for (int c = 0; c < 6; c++) a[c] = d_csum[c] * (1.0f / (float)CH);
    float t1[30];
    for (int o = 0; o < 30; o++) {
        float s = fc1b[o];
#pragma unroll
        for (int c = 0; c < 6; c++) s += fc1w[o*6 + c] * a[c];
        t1[o] = s > 0.0f ? s : 0.0f;
    }
    for (int c = 0; c < 6; c++) {
        float s = fc2b[c];
        for (int o = 0; o < 30; o++) s += fc2w[c*30 + o] * t1[o];
        d_att[c] = 1.0f / (1.0f + expf(-s));
    }
}

// Fused combine + transpose.
// F == flat(d_XM): val(d,n) = conv_b + sum_c conv_w[c] * relu(att[c] * F[c*CH + d*NN + n])
// Output is out[n, d] (N x 64). Block: 32 nodes x 64 dims via (32,32) threads x 2.
__global__ void __launch_bounds__(1024) k_combine_tr(const float* __restrict__ convw,
                                                     const float* __restrict__ convb,
                                                     float* __restrict__ out) {
    __shared__ float tile[64][33];
    float at[6], cw[6];
#pragma unroll
    for (int c = 0; c < 6; c++) { at[c] = d_att[c]; cw[c] = convw[c]; }
    float cb = convb[0];
    int n0 = blockIdx.x * 32;
    int n = n0 + threadIdx.x;
#pragma unroll
    for (int h = 0; h < 2; h++) {
        int d = threadIdx.y + h * 32;
        float acc = cb;
#pragma unroll
        for (int c = 0; c < 6; c++) {
            float v = d_XM[(size_t)c*CH + (size_t)d*NN + n];
            acc += cw[c] * fmaxf(at[c] * v, 0.0f);
        }
        tile[d][threadIdx.x] = acc;
    }
    __syncthreads();
    int n2 = n0 + threadIdx.y;
#pragma unroll
    for (int h = 0; h < 2; h++) {
        int d2 = threadIdx.x + h * 32;
        out[(size_t)n2 * 64 + d2] = tile[d2][threadIdx.y];
    }
}

// ---------------- host ------------------------------------------------------

extern "C" void kernel_launch(void* const* d_in, const int* in_sizes, int n_in,
                              void* d_out, int out_size) {
    // Identify inputs by element count + order of appearance (robust to
    // dict-order vs signature-order metadata; both preserve relative order).
    const float* x = nullptr;
    const float* w[3] = {nullptr, nullptr, nullptr};
    const int*   ed[3] = {nullptr, nullptr, nullptr};
    const float *W1 = nullptr, *b1 = nullptr, *W2 = nullptr, *b2 = nullptr;
    const float *fc1w = nullptr, *fc1b = nullptr, *fc2w = nullptr, *fc2b = nullptr;
    const float *cw = nullptr, *cb = nullptr;
    int iw = 0, ie = 0;
    for (int i = 0; i < n_in; i++) {
        int s = in_sizes[i];
        if (s == NN*DD) {                    // 6.4M: x first, then edges_g,c,f
            if (!x) x = (const float*)d_in[i];
            else if (ie < 3) ed[ie++] = (const int*)d_in[i];
        } else if (s == EE) {                // 3.2M: w_g, w_c, w_f
            if (iw < 3) w[iw++] = (const float*)d_in[i];
        } else if (s == 4096) { if (!W1) W1 = (const float*)d_in[i]; else W2 = (const float*)d_in[i]; }
        else if (s == 64)   { if (!b1) b1 = (const float*)d_in[i]; else b2 = (const float*)d_in[i]; }
        else if (s == 180)  { if (!fc1w) fc1w = (const float*)d_in[i]; else fc2w = (const float*)d_in[i]; }
        else if (s == 30)   { fc1b = (const float*)d_in[i]; }
        else if (s == 6)    { if (!fc2b) fc2b = (const float*)d_in[i]; else cw = (const float*)d_in[i]; }
        else if (s == 1)    { cb = (const float*)d_in[i]; }
    }

    const int B = 256;
    k_init<<<(3*NN + B-1)/B, B>>>();
    for (int g = 0; g < 3; g++)
        k_deg<<<(EE + B-1)/B, B>>>(ed[g] + EE, w[g], g);
    k_dinv<<<(3*NN + B-1)/B, B>>>();
    for (int g = 0; g < 3; g++)
        k_norm<<<(EE + B-1)/B, B>>>(ed[g], ed[g] + EE, w[g], g);

    // layer 1: h1 = x @ W1 shared across graphs
    k_gemm<<<(NN + 127)/128, 128>>>(x, 0, 0, W1);
    for (int g = 0; g < 3; g++) {
        int off = g * 128;                    // g1/c1/f1 slots
        k_initacc<<<(CH + B-1)/B, B>>>(g, b1);
        k_scatter<<<(EE*16)/B, B>>>(ed[g], ed[g] + EE, g);
        k_relu_store<<<(CH + B-1)/B, B>>>(off);
    }
    // layer 2 per graph: h2 = (layer-1 slot) @ W2
    for (int g = 0; g < 3; g++) {
        int off = g * 128 + 64;               // g2/c2/f2 slots
        k_gemm<<<(NN + 127)/128, 128>>>(nullptr, 1, g*128, W2);
        k_initacc<<<(CH + B-1)/B, B>>>(g, b2);
        k_scatter<<<(EE*16)/B, B>>>(ed[g], ed[g] + EE, g);
        k_relu_store<<<(CH + B-1)/B, B>>>(off);
    }

    k_csum<<<((6*CH)/16 + B-1)/B, B>>>();
    k_mlp<<<1, 32>>>(fc1w, fc1b, fc2w, fc2b);
    k_combine_tr<<<NN/32, dim3(32, 32)>>>(cw, cb, (float*)d_out);
    (void)out_size; (void)n_in;
}

// round 8
// speedup vs baseline: 1.4442x; 1.4442x over previous
#include <cuda_runtime.h>
#include <math.h>

#define NN 100000
#define EE 3200000
#define DD 64
#define CH (NN*DD)          // elements per XM chunk
#define XMW 384             // 6*64 columns in concat buffer

// ---------------- scratch (static device allocations) -----------------------
__device__ float d_deg[3*NN];            // weighted degree (init 1.0 self-loop)
__device__ int   d_cnt[3*NN];            // integer in-degree (no self-loop)
__device__ float d_dinv[3*NN];
__device__ int   d_ptr[3*(NN+1)];        // CSR row pointers (by dst)
__device__ int   d_cur[3*NN];            // fill cursors
__device__ int   d_csr_src[3*EE];        // 38.4 MB
__device__ float d_csr_nrm[3*EE];        // 38.4 MB
__device__ float d_h[NN*DD];             // dense GEMM output (25.6 MB, L2-resident)
__device__ float d_XM[(size_t)NN*XMW];   // concat(g1,g2,c1,c2,f1,f2) [N,384]
__device__ float d_csum[6];
__device__ float d_att[6];

// ---------------- kernels ---------------------------------------------------

__global__ void k_init() {
    int t = blockIdx.x * 256 + threadIdx.x;
    if (t < 3*NN) { d_deg[t] = 1.0f; d_cnt[t] = 0; }
    if (t < 6)    d_csum[t] = 0.0f;
}

// fused weighted degree + integer count per destination
__global__ void k_cnt_deg(const int* __restrict__ cols, const float* __restrict__ w, int g) {
    int t = blockIdx.x * 256 + threadIdx.x;
    if (t < EE) {
        int c = cols[t];
        atomicAdd(&d_deg[g*NN + c], w[t]);
        atomicAdd(&d_cnt[g*NN + c], 1);
    }
}

__global__ void k_dinv() {
    int t = blockIdx.x * 256 + threadIdx.x;
    if (t < 3*NN) {
        float d = d_deg[t];
        d_dinv[t] = (d > 0.0f) ? rsqrtf(d) : 0.0f;
    }
}

// exclusive scan of d_cnt -> d_ptr / d_cur. One block per graph, 1024 threads.
__global__ void __launch_bounds__(1024) k_scan() {
    __shared__ int sums[1024];
    int g = blockIdx.x;
    int t = threadIdx.x;
    const int CPT = (NN + 1023) / 1024;   // 98
    int begin = t * CPT;
    int end = begin + CPT; if (end > NN) end = NN;
    int s = 0;
    for (int i = begin; i < end; i++) s += d_cnt[g*NN + i];
    sums[t] = s;
    __syncthreads();
    for (int off = 1; off < 1024; off <<= 1) {
        int v = 0;
        if (t >= off) v = sums[t - off];
        __syncthreads();
        if (t >= off) sums[t] += v;
        __syncthreads();
    }
    int run = sums[t] - s;                 // exclusive prefix
    for (int i = begin; i < end; i++) {
        d_ptr[g*(NN+1) + i] = run;
        d_cur[g*NN + i] = run;
        run += d_cnt[g*NN + i];
    }
    if (t == 0) d_ptr[g*(NN+1) + NN] = EE;
}

// fill CSR: (src, norm) pairs grouped by destination; norm computed inline
__global__ void k_fill(const int* __restrict__ rows, const int* __restrict__ cols,
                       const float* __restrict__ w, int g) {
    int t = blockIdx.x * 256 + threadIdx.x;
    if (t >= EE) return;
    int r = rows[t], c = cols[t];
    float nm = d_dinv[g*NN + r] * w[t] * d_dinv[g*NN + c];
    int pos = atomicAdd(&d_cur[g*NN + c], 1);
    d_csr_src[(size_t)g*EE + pos] = r;
    d_csr_nrm[(size_t)g*EE + pos] = nm;
}

// H[N,64] = X @ W. src=0: external x [N,64]; src=1: XM slot at column xmoff.
__global__ void __launch_bounds__(128) k_gemm(const float* __restrict__ X, int src, int xmoff,
                                              const float* __restrict__ W) {
    __shared__ float Ws[64*64];
    int tid = threadIdx.x;
    for (int i = tid; i < 64*64; i += 128) Ws[i] = W[i];
    __syncthreads();
    int row = blockIdx.x * 128 + tid;
    if (row >= NN) return;
    const float* xr = src ? (d_XM + (size_t)row * XMW + xmoff)
                          : (X + (size_t)row * DD);
    float acc[64];
#pragma unroll
    for (int j = 0; j < 64; j++) acc[j] = 0.0f;
    for (int k = 0; k < 64; k++) {
        float xv = xr[k];
        const float4* wr = (const float4*)(Ws + k*64);
#pragma unroll
        for (int j4 = 0; j4 < 16; j4++) {
            float4 wv = wr[j4];
            acc[j4*4+0] += xv * wv.x;
            acc[j4*4+1] += xv * wv.y;
            acc[j4*4+2] += xv * wv.z;
            acc[j4*4+3] += xv * wv.w;
        }
    }
    float4* hr = (float4*)(d_h + (size_t)row * 64);
#pragma unroll
    for (int j4 = 0; j4 < 16; j4++)
        hr[j4] = make_float4(acc[j4*4], acc[j4*4+1], acc[j4*4+2], acc[j4*4+3]);
}

// CSR gather aggregation, fused with bias+self-loop init, ReLU, XM store.
// One warp per node; 32 lanes x float2 = 64 dims. Inner loop software-
// pipelined: (src,norm) for iteration j+1 prefetched during j's gather.
__global__ void __launch_bounds__(128) k_gather(int g, int off, const float* __restrict__ b) {
    int warp = (blockIdx.x * 128 + threadIdx.x) >> 5;
    int lane = threadIdx.x & 31;
    if (warp >= NN) return;
    int n = warp;
    int beg  = __ldg(&d_ptr[g*(NN+1) + n]);
    int end2 = __ldg(&d_ptr[g*(NN+1) + n + 1]);
    float dv = d_dinv[g*NN + n];
    float2 hv = *(const float2*)(d_h + (size_t)n*64 + lane*2);
    float2 acc;
    acc.x = b[lane*2]     + dv*dv*hv.x;
    acc.y = b[lane*2 + 1] + dv*dv*hv.y;
    const int*   srcp = d_csr_src + (size_t)g*EE;
    const float* nrmp = d_csr_nrm + (size_t)g*EE;
    if (beg < end2) {
        int   sj = __ldg(srcp + beg);     // broadcast (all lanes same addr)
        float nj = __ldg(nrmp + beg);
        for (int j = beg + 1; j < end2; j++) {
            int   sn = __ldg(srcp + j);
            float nn = __ldg(nrmp + j);
            float2 v = *(const float2*)(d_h + (size_t)sj*64 + lane*2);
            acc.x += nj * v.x;
            acc.y += nj * v.y;
            sj = sn; nj = nn;
        }
        float2 v = *(const float2*)(d_h + (size_t)sj*64 + lane*2);
        acc.x += nj * v.x;
        acc.y += nj * v.y;
    }
    float rx = fmaxf(acc.x, 0.0f), ry = fmaxf(acc.y, 0.0f);
    *(float2*)(d_XM + (size_t)n*XMW + off + lane*2) = make_float2(rx, ry);
}

// per-chunk sums over the FLAT d_XM buffer (chunk = flat_index / CH).
// This matches the reference's reshape(1,6,D,N).mean(axis=(2,3)), which
// mixes rows/slots — chunk boundaries are flat ranges, NOT column slots.
// 16 elems/thread; CH % 16 == 0, so no thread straddles a chunk boundary.
__global__ void k_csum() {
    int t = blockIdx.x * 256 + threadIdx.x;   // 2.4M threads
    size_t base = (size_t)t * 16;
    int chunk = (int)(base / (size_t)CH);
    const float4* p = (const float4*)(d_XM + base);
    float s = 0.0f;
#pragma unroll
    for (int i = 0; i < 4; i++) { float4 v = p[i]; s += v.x + v.y + v.z + v.w; }
#pragma unroll
    for (int o = 16; o > 0; o >>= 1) s += __shfl_down_sync(0xffffffffu, s, o);
    if ((threadIdx.x & 31) == 0) atomicAdd(&d_csum[chunk], s);
}

__global__ void k_mlp(const float* __restrict__ fc1w, const float* __restrict__ fc1b,
                      const float* __restrict__ fc2w, const float* __restrict__ fc2b) {
    if (threadIdx.x != 0 || blockIdx.x != 0) return;
    float a[6];
#pragma unroll
    for (int c = 0; c < 6; c++) a[c] = d_csum[c] * (1.0f / (float)CH);
    float t1[30];
    for (int o = 0; o < 30; o++) {
        float s = fc1b[o];
#pragma unroll
        for (int c = 0; c < 6; c++) s += fc1w[o*6 + c] * a[c];
        t1[o] = s > 0.0f ? s : 0.0f;
    }
    for (int c = 0; c < 6; c++) {
        float s = fc2b[c];
        for (int o = 0; o < 30; o++) s += fc2w[c*30 + o] * t1[o];
        d_att[c] = 1.0f / (1.0f + expf(-s));
    }
}

// Fused combine + transpose.
// F == flat(d_XM): val(d,n) = conv_b + sum_c conv_w[c] * relu(att[c] * F[c*CH + d*NN + n])
__global__ void __launch_bounds__(1024) k_combine_tr(const float* __restrict__ convw,
                                                     const float* __restrict__ convb,
                                                     float* __restrict__ out) {
    __shared__ float tile[64][33];
    float at[6], cw[6];
#pragma unroll
    for (int c = 0; c < 6; c++) { at[c] = d_att[c]; cw[c] = convw[c]; }
    float cb = convb[0];
    int n0 = blockIdx.x * 32;
    int n = n0 + threadIdx.x;
#pragma unroll
    for (int h = 0; h < 2; h++) {
        int d = threadIdx.y + h * 32;
        float acc = cb;
#pragma unroll
        for (int c = 0; c < 6; c++) {
            float v = d_XM[(size_t)c*CH + (size_t)d*NN + n];
            acc += cw[c] * fmaxf(at[c] * v, 0.0f);
        }
        tile[d][threadIdx.x] = acc;
    }
    __syncthreads();
    int n2 = n0 + threadIdx.y;
#pragma unroll
    for (int h = 0; h < 2; h++) {
        int d2 = threadIdx.x + h * 32;
        out[(size_t)n2 * 64 + d2] = tile[d2][threadIdx.y];
    }
}

// ---------------- host ------------------------------------------------------

extern "C" void kernel_launch(void* const* d_in, const int* in_sizes, int n_in,
                              void* d_out, int out_size) {
    const float* x = nullptr;
    const float* w[3] = {nullptr, nullptr, nullptr};
    const int*   ed[3] = {nullptr, nullptr, nullptr};
    const float *W1 = nullptr, *b1 = nullptr, *W2 = nullptr, *b2 = nullptr;
    const float *fc1w = nullptr, *fc1b = nullptr, *fc2w = nullptr, *fc2b = nullptr;
    const float *cw = nullptr, *cb = nullptr;
    int iw = 0, ie = 0;
    for (int i = 0; i < n_in; i++) {
        int s = in_sizes[i];
        if (s == NN*DD) {                    // 6.4M: x first, then edges_g,c,f
            if (!x) x = (const float*)d_in[i];
            else if (ie < 3) ed[ie++] = (const int*)d_in[i];
        } else if (s == EE) {                // 3.2M: w_g, w_c, w_f
            if (iw < 3) w[iw++] = (const float*)d_in[i];
        } else if (s == 4096) { if (!W1) W1 = (const float*)d_in[i]; else W2 = (const float*)d_in[i]; }
        else if (s == 64)   { if (!b1) b1 = (const float*)d_in[i]; else b2 = (const float*)d_in[i]; }
        else if (s == 180)  { if (!fc1w) fc1w = (const float*)d_in[i]; else fc2w = (const float*)d_in[i]; }
        else if (s == 30)   { fc1b = (const float*)d_in[i]; }
        else if (s == 6)    { if (!fc2b) fc2b = (const float*)d_in[i]; else cw = (const float*)d_in[i]; }
        else if (s == 1)    { cb = (const float*)d_in[i]; }
    }

    const int B = 256;
    const int GW = (NN*32 + 127)/128;        // gather grid: 1 warp per node, 128-thr blocks

    k_init<<<(3*NN + B-1)/B, B>>>();
    for (int g = 0; g < 3; g++)
        k_cnt_deg<<<(EE + B-1)/B, B>>>(ed[g] + EE, w[g], g);
    k_dinv<<<(3*NN + B-1)/B, B>>>();
    k_scan<<<3, 1024>>>();
    for (int g = 0; g < 3; g++)
        k_fill<<<(EE + B-1)/B, B>>>(ed[g], ed[g] + EE, w[g], g);

    // layer 1: h1 = x @ W1 shared across all three graphs
    k_gemm<<<(NN + 127)/128, 128>>>(x, 0, 0, W1);
    for (int g = 0; g < 3; g++)
        k_gather<<<GW, 128>>>(g, g*128, b1);        // g1/c1/f1 slots
    // layer 2 per graph: h2 = (layer-1 slot) @ W2
    for (int g = 0; g < 3; g++) {
        k_gemm<<<(NN + 127)/128, 128>>>(nullptr, 1, g*128, W2);
        k_gather<<<GW, 128>>>(g, g*128 + 64, b2);   // g2/c2/f2 slots
    }

    k_csum<<<((6*CH)/16 + B-1)/B, B>>>();
    k_mlp<<<1, 32>>>(fc1w, fc1b, fc2w, fc2b);
    k_combine_tr<<<NN/32, dim3(32, 32)>>>(cw, cb, (float*)d_out);
    (void)out_size; (void)n_in;
}

// round 9
// speedup vs baseline: 1.5976x; 1.1062x over previous
#include <cuda_runtime.h>
#include <math.h>

#define NN 100000
#define EE 3200000
#define DD 64
#define CH (NN*DD)          // elements per XM chunk
#define XMW 384             // 6*64 columns in concat buffer

// ---------------- scratch (static device allocations) -----------------------
__device__ float d_deg[3*NN];            // weighted degree (init 1.0 self-loop)
__device__ int   d_cnt[3*NN];            // integer in-degree (no self-loop)
__device__ float d_dinv[3*NN];
__device__ int   d_ptr[3*(NN+1)];        // CSR row pointers (by dst)
__device__ int   d_cur[3*NN];            // fill cursors
__device__ int2  d_csr[3*EE];            // interleaved (src, norm-bits), 76.8 MB
__device__ float d_h[NN*DD];             // dense GEMM output (25.6 MB, L2-resident)
__device__ float d_XM[(size_t)NN*XMW];   // concat(g1,g2,c1,c2,f1,f2) [N,384]
__device__ float d_csum[6];
__device__ float d_att[6];

// ---------------- kernels ---------------------------------------------------

__global__ void k_init() {
    int t = blockIdx.x * 256 + threadIdx.x;
    if (t < 3*NN) { d_deg[t] = 1.0f; d_cnt[t] = 0; }
    if (t < 6)    d_csum[t] = 0.0f;
}

// fused weighted degree + integer count per destination
__global__ void k_cnt_deg(const int* __restrict__ cols, const float* __restrict__ w, int g) {
    int t = blockIdx.x * 256 + threadIdx.x;
    if (t < EE) {
        int c = cols[t];
        atomicAdd(&d_deg[g*NN + c], w[t]);
        atomicAdd(&d_cnt[g*NN + c], 1);
    }
}

__global__ void k_dinv() {
    int t = blockIdx.x * 256 + threadIdx.x;
    if (t < 3*NN) {
        float d = d_deg[t];
        d_dinv[t] = (d > 0.0f) ? rsqrtf(d) : 0.0f;
    }
}

// exclusive scan of d_cnt -> d_ptr / d_cur. One block per graph, 1024 threads.
__global__ void __launch_bounds__(1024) k_scan() {
    __shared__ int sums[1024];
    int g = blockIdx.x;
    int t = threadIdx.x;
    const int CPT = (NN + 1023) / 1024;   // 98
    int begin = t * CPT;
    int end = begin + CPT; if (end > NN) end = NN;
    int s = 0;
    for (int i = begin; i < end; i++) s += d_cnt[g*NN + i];
    sums[t] = s;
    __syncthreads();
    for (int off = 1; off < 1024; off <<= 1) {
        int v = 0;
        if (t >= off) v = sums[t - off];
        __syncthreads();
        if (t >= off) sums[t] += v;
        __syncthreads();
    }
    int run = sums[t] - s;                 // exclusive prefix
    for (int i = begin; i < end; i++) {
        d_ptr[g*(NN+1) + i] = run;
        d_cur[g*NN + i] = run;
        run += d_cnt[g*NN + i];
    }
    if (t == 0) d_ptr[g*(NN+1) + NN] = EE;
}

// fill CSR: one interleaved (src, norm) 8-byte record per edge
__global__ void k_fill(const int* __restrict__ rows, const int* __restrict__ cols,
                       const float* __restrict__ w, int g) {
    int t = blockIdx.x * 256 + threadIdx.x;
    if (t >= EE) return;
    int r = rows[t], c = cols[t];
    float nm = d_dinv[g*NN + r] * w[t] * d_dinv[g*NN + c];
    int pos = atomicAdd(&d_cur[g*NN + c], 1);
    d_csr[(size_t)g*EE + pos] = make_int2(r, __float_as_int(nm));
}

// H[N,64] = X @ W. src=0: external x [N,64]; src=1: XM slot at column xmoff.
__global__ void __launch_bounds__(128) k_gemm(const float* __restrict__ X, int src, int xmoff,
                                              const float* __restrict__ W) {
    __shared__ float Ws[64*64];
    int tid = threadIdx.x;
    for (int i = tid; i < 64*64; i += 128) Ws[i] = W[i];
    __syncthreads();
    int row = blockIdx.x * 128 + tid;
    if (row >= NN) return;
    const float* xr = src ? (d_XM + (size_t)row * XMW + xmoff)
                          : (X + (size_t)row * DD);
    float acc[64];
#pragma unroll
    for (int j = 0; j < 64; j++) acc[j] = 0.0f;
    for (int k = 0; k < 64; k++) {
        float xv = xr[k];
        const float4* wr = (const float4*)(Ws + k*64);
#pragma unroll
        for (int j4 = 0; j4 < 16; j4++) {
            float4 wv = wr[j4];
            acc[j4*4+0] += xv * wv.x;
            acc[j4*4+1] += xv * wv.y;
            acc[j4*4+2] += xv * wv.z;
            acc[j4*4+3] += xv * wv.w;
        }
    }
    float4* hr = (float4*)(d_h + (size_t)row * 64);
#pragma unroll
    for (int j4 = 0; j4 < 16; j4++)
        hr[j4] = make_float4(acc[j4*4], acc[j4*4+1], acc[j4*4+2], acc[j4*4+3]);
}

// CSR gather aggregation, fused with bias+self-loop init, ReLU, XM store.
// One warp per node; 32 lanes x float2 = 64 dims. Inner loop unrolled 4x
// with independent feature loads (MLP=4 on the d_h gather).
// g = gbase + blockIdx.y, off = offbase + blockIdx.y*128 (layer-1 fuses
// all three graphs in one launch via gridDim.y = 3).
__global__ void __launch_bounds__(256) k_gather(int gbase, int offbase,
                                                const float* __restrict__ b) {
    int warp = (blockIdx.x * 256 + threadIdx.x) >> 5;
    int lane = threadIdx.x & 31;
    if (warp >= NN) return;
    int g   = gbase + blockIdx.y;
    int off = offbase + blockIdx.y * 128;
    int n = warp;
    int beg  = __ldg(&d_ptr[g*(NN+1) + n]);
    int end2 = __ldg(&d_ptr[g*(NN+1) + n + 1]);
    float dv = d_dinv[g*NN + n];
    float2 hv = *(const float2*)(d_h + (size_t)n*64 + lane*2);
    float2 acc;
    acc.x = b[lane*2]     + dv*dv*hv.x;
    acc.y = b[lane*2 + 1] + dv*dv*hv.y;
    const int2* csr = d_csr + (size_t)g*EE;
    int j = beg;
    for (; j + 4 <= end2; j += 4) {
        int2 e0 = __ldg(csr + j);
        int2 e1 = __ldg(csr + j + 1);
        int2 e2 = __ldg(csr + j + 2);
        int2 e3 = __ldg(csr + j + 3);
        float2 v0 = *(const float2*)(d_h + (size_t)e0.x*64 + lane*2);
        float2 v1 = *(const float2*)(d_h + (size_t)e1.x*64 + lane*2);
        float2 v2 = *(const float2*)(d_h + (size_t)e2.x*64 + lane*2);
        float2 v3 = *(const float2*)(d_h + (size_t)e3.x*64 + lane*2);
        float n0 = __int_as_float(e0.y), n1 = __int_as_float(e1.y);
        float n2 = __int_as_float(e2.y), n3 = __int_as_float(e3.y);
        acc.x += n0*v0.x + n1*v1.x + n2*v2.x + n3*v3.x;
        acc.y += n0*v0.y + n1*v1.y + n2*v2.y + n3*v3.y;
    }
    for (; j < end2; j++) {
        int2 e = __ldg(csr + j);
        float2 v = *(const float2*)(d_h + (size_t)e.x*64 + lane*2);
        float nm = __int_as_float(e.y);
        acc.x += nm * v.x;
        acc.y += nm * v.y;
    }
    float rx = fmaxf(acc.x, 0.0f), ry = fmaxf(acc.y, 0.0f);
    *(float2*)(d_XM + (size_t)n*XMW + off + lane*2) = make_float2(rx, ry);
}

// per-chunk sums over the FLAT d_XM buffer (chunk = flat_index / CH).
// This matches the reference's reshape(1,6,D,N).mean(axis=(2,3)), which
// mixes rows/slots — chunk boundaries are flat ranges, NOT column slots.
// 16 elems/thread; CH % 16 == 0, so no thread straddles a chunk boundary.
__global__ void k_csum() {
    int t = blockIdx.x * 256 + threadIdx.x;   // 2.4M threads
    size_t base = (size_t)t * 16;
    int chunk = (int)(base / (size_t)CH);
    const float4* p = (const float4*)(d_XM + base);
    float s = 0.0f;
#pragma unroll
    for (int i = 0; i < 4; i++) { float4 v = p[i]; s += v.x + v.y + v.z + v.w; }
#pragma unroll
    for (int o = 16; o > 0; o >>= 1) s += __shfl_down_sync(0xffffffffu, s, o);
    if ((threadIdx.x & 31) == 0) atomicAdd(&d_csum[chunk], s);
}

__global__ void k_mlp(const float* __restrict__ fc1w, const float* __restrict__ fc1b,
                      const float* __restrict__ fc2w, const float* __restrict__ fc2b) {
    if (threadIdx.x != 0 || blockIdx.x != 0) return;
    float a[6];
#pragma unroll
    for (int c = 0; c < 6; c++) a[c] = d_csum[c] * (1.0f / (float)CH);
    float t1[30];
    for (int o = 0; o < 30; o++) {
        float s = fc1b[o];
#pragma unroll
        for (int c = 0; c < 6; c++) s += fc1w[o*6 + c] * a[c];
        t1[o] = s > 0.0f ? s : 0.0f;
    }
    for (int c = 0; c < 6; c++) {
        float s = fc2b[c];
        for (int o = 0; o < 30; o++) s += fc2w[c*30 + o] * t1[o];
        d_att[c] = 1.0f / (1.0f + expf(-s));
    }
}

// Fused combine + transpose.
// F == flat(d_XM): val(d,n) = conv_b + sum_c conv_w[c] * relu(att[c] * F[c*CH + d*NN + n])
__global__ void __launch_bounds__(1024) k_combine_tr(const float* __restrict__ convw,
                                                     const float* __restrict__ convb,
                                                     float* __restrict__ out) {
    __shared__ float tile[64][33];
    float at[6], cw[6];
#pragma unroll
    for (int c = 0; c < 6; c++) { at[c] = d_att[c]; cw[c] = convw[c]; }
    float cb = convb[0];
    int n0 = blockIdx.x * 32;
    int n = n0 + threadIdx.x;
#pragma unroll
    for (int h = 0; h < 2; h++) {
        int d = threadIdx.y + h * 32;
        float acc = cb;
#pragma unroll
        for (int c = 0; c < 6; c++) {
            float v = d_XM[(size_t)c*CH + (size_t)d*NN + n];
            acc += cw[c] * fmaxf(at[c] * v, 0.0f);
        }
        tile[d][threadIdx.x] = acc;
    }
    __syncthreads();
    int n2 = n0 + threadIdx.y;
#pragma unroll
    for (int h = 0; h < 2; h++) {
        int d2 = threadIdx.x + h * 32;
        out[(size_t)n2 * 64 + d2] = tile[d2][threadIdx.y];
    }
}

// ---------------- host ------------------------------------------------------

extern "C" void kernel_launch(void* const* d_in, const int* in_sizes, int n_in,
                              void* d_out, int out_size) {
    const float* x = nullptr;
    const float* w[3] = {nullptr, nullptr, nullptr};
    const int*   ed[3] = {nullptr, nullptr, nullptr};
    const float *W1 = nullptr, *b1 = nullptr, *W2 = nullptr, *b2 = nullptr;
    const float *fc1w = nullptr, *fc1b = nullptr, *fc2w = nullptr, *fc2b = nullptr;
    const float *cw = nullptr, *cb = nullptr;
    int iw = 0, ie = 0;
    for (int i = 0; i < n_in; i++) {
        int s = in_sizes[i];
        if (s == NN*DD) {                    // 6.4M: x first, then edges_g,c,f
            if (!x) x = (const float*)d_in[i];
            else if (ie < 3) ed[ie++] = (const int*)d_in[i];
        } else if (s == EE) {                // 3.2M: w_g, w_c, w_f
            if (iw < 3) w[iw++] = (const float*)d_in[i];
        } else if (s == 4096) { if (!W1) W1 = (const float*)d_in[i]; else W2 = (const float*)d_in[i]; }
        else if (s == 64)   { if (!b1) b1 = (const float*)d_in[i]; else b2 = (const float*)d_in[i]; }
        else if (s == 180)  { if (!fc1w) fc1w = (const float*)d_in[i]; else fc2w = (const float*)d_in[i]; }
        else if (s == 30)   { fc1b = (const float*)d_in[i]; }
        else if (s == 6)    { if (!fc2b) fc2b = (const float*)d_in[i]; else cw = (const float*)d_in[i]; }
        else if (s == 1)    { cb = (const float*)d_in[i]; }
    }

    const int B = 256;
    const int GW = (NN*32 + 255)/256;        // gather grid.x: 1 warp per node

    k_init<<<(3*NN + B-1)/B, B>>>();
    for (int g = 0; g < 3; g++)
        k_cnt_deg<<<(EE + B-1)/B, B>>>(ed[g] + EE, w[g], g);
    k_dinv<<<(3*NN + B-1)/B, B>>>();
    k_scan<<<3, 1024>>>();
    for (int g = 0; g < 3; g++)
        k_fill<<<(EE + B-1)/B, B>>>(ed[g], ed[g] + EE, w[g], g);

    // layer 1: h1 = x @ W1 shared across all three graphs; fused 3-graph gather
    k_gemm<<<(NN + 127)/128, 128>>>(x, 0, 0, W1);
    k_gather<<<dim3(GW, 3), B>>>(0, 0, b1);          // g1/c1/f1 slots (off = g*128)
    // layer 2 per graph: h2 = (layer-1 slot) @ W2
    for (int g = 0; g < 3; g++) {
        k_gemm<<<(NN + 127)/128, 128>>>(nullptr, 1, g*128, W2);
        k_gather<<<dim3(GW, 1), B>>>(g, g*128 + 64, b2);   // g2/c2/f2 slots
    }

    k_csum<<<((6*CH)/16 + B-1)/B, B>>>();
    k_mlp<<<1, 32>>>(fc1w, fc1b, fc2w, fc2b);
    k_combine_tr<<<NN/32, dim3(32, 32)>>>(cw, cb, (float*)d_out);
    (void)out_size; (void)n_in;
}